// round 10
// baseline (speedup 1.0000x reference)
#include <cuda_runtime.h>
#include <cuda_bf16.h>
#include <stdint.h>
#include <math.h>

#define N_NODES_MAX 16384
#define IN_DIM 512
#define MEM_DIM 256
#define VOCAB 64
#define MAX_CH 8

// Scratch (allocation-free rule: __device__ globals)
__device__ float g_X[N_NODES_MAX * MEM_DIM];            // inputs @ W_in^T + b (internal rows)
__device__ float g_P[N_NODES_MAX * MEM_DIM];            // states @ W_ch^T (per level)
__device__ float g_D[VOCAB * MEM_DIM];                  // deprel_emb @ W_dep^T
__device__ __nv_bfloat16 g_Wh[MEM_DIM * 1024];          // W split hi
__device__ __nv_bfloat16 g_Wl[MEM_DIM * 1024];          // W split lo
__device__ __nv_bfloat16 g_Sh[N_NODES_MAX * MEM_DIM];   // states split hi
__device__ __nv_bfloat16 g_Sl[N_NODES_MAX * MEM_DIM];   // states split lo

#define AROW 24   // bf16 elems per smem row: 16 data + 8 pad (48B, 16B-aligned)

__device__ __forceinline__ void ldsm4(unsigned& r0, unsigned& r1,
                                      unsigned& r2, unsigned& r3, unsigned addr) {
    asm volatile("ldmatrix.sync.aligned.m8n8.x4.shared.b16 {%0,%1,%2,%3}, [%4];"
                 : "=r"(r0), "=r"(r1), "=r"(r2), "=r"(r3) : "r"(addr));
}

__device__ __forceinline__ void mma16816(float* c,
                                         unsigned a0, unsigned a1, unsigned a2, unsigned a3,
                                         unsigned b0, unsigned b1) {
    asm volatile(
        "mma.sync.aligned.m16n8k16.row.col.f32.bf16.bf16.f32 "
        "{%0,%1,%2,%3}, {%4,%5,%6,%7}, {%8,%9}, {%0,%1,%2,%3};"
        : "+f"(c[0]), "+f"(c[1]), "+f"(c[2]), "+f"(c[3])
        : "r"(a0), "r"(a1), "r"(a2), "r"(a3), "r"(b0), "r"(b1));
}

__device__ __forceinline__ void split2(float x, float y,
                                       __nv_bfloat162& hi, __nv_bfloat162& lo) {
    __nv_bfloat16 hx = __float2bfloat16(x);
    __nv_bfloat16 hy = __float2bfloat16(y);
    hi = __halves2bfloat162(hx, hy);
    lo = __halves2bfloat162(__float2bfloat16(x - __bfloat162float(hx)),
                            __float2bfloat16(y - __bfloat162float(hy)));
}

__device__ __forceinline__ void store_a8(__nv_bfloat16* hb, __nv_bfloat16* lb,
                                         int row, int k, float4 v0, float4 v1) {
    __nv_bfloat162 h, l;
    __nv_bfloat162* hp = (__nv_bfloat162*)(hb + row * AROW + k);
    __nv_bfloat162* lp = (__nv_bfloat162*)(lb + row * AROW + k);
    split2(v0.x, v0.y, h, l); hp[0] = h; lp[0] = l;
    split2(v0.z, v0.w, h, l); hp[1] = h; lp[1] = l;
    split2(v1.x, v1.y, h, l); hp[2] = h; lp[2] = l;
    split2(v1.z, v1.w, h, l); hp[3] = h; lp[3] = l;
}

// one-time W split: 256x1024 fp32 -> bf16 hi/lo
__global__ __launch_bounds__(256)
void split_w(const float* __restrict__ W,
             __nv_bfloat16* __restrict__ Wh, __nv_bfloat16* __restrict__ Wl) {
    int i = (blockIdx.x * 256 + threadIdx.x) * 4;   // 256 blocks -> 262144 elems
    float4 v = *(const float4*)(W + i);
    __nv_bfloat162 h, l;
    split2(v.x, v.y, h, l);
    ((__nv_bfloat162*)(Wh + i))[0] = h; ((__nv_bfloat162*)(Wl + i))[0] = l;
    split2(v.z, v.w, h, l);
    ((__nv_bfloat162*)(Wh + i))[1] = h; ((__nv_bfloat162*)(Wl + i))[1] = l;
}

// ---------------------------------------------------------------------------
// C[m,n] = sum_k A[m,k] * W[n, wofs+k]  (+ bias[n])
// Split-bf16 3-pass tensor GEMM. Block 128(M) x 128(N), BK=16 double-buffered,
// 8 warps (4Mx2N), warp tile 32x64. B always pre-split (g_Wh/g_Wl).
// A_SPLIT: A pre-split bf16 (Agh/Agl); else fp32 A split inline in loader.
// LEAF_TANH: rows >= first_leaf -> tanh to S and split copies Sh/Sl.
// ---------------------------------------------------------------------------
template<bool A_SPLIT, bool HAS_BIAS, bool LEAF_TANH>
__global__ __launch_bounds__(256)
void rcnn_gemm_mma(const float* __restrict__ A,
                   const __nv_bfloat16* __restrict__ Agh,
                   const __nv_bfloat16* __restrict__ Agl, int lda,
                   const __nv_bfloat16* __restrict__ Wh,
                   const __nv_bfloat16* __restrict__ Wl, int wofs,
                   const float* __restrict__ bias,
                   float* __restrict__ Cmat, int M, int K,
                   float* __restrict__ S,
                   __nv_bfloat16* __restrict__ Sh,
                   __nv_bfloat16* __restrict__ Sl, int first_leaf) {
    __shared__ __nv_bfloat16 sAh[2][128 * AROW];
    __shared__ __nv_bfloat16 sAl[2][128 * AROW];
    __shared__ __nv_bfloat16 sBh[2][128 * AROW];
    __shared__ __nv_bfloat16 sBl[2][128 * AROW];

    const int tid  = threadIdx.x;
    const int lane = tid & 31;
    const int warp = tid >> 5;
    const int wm   = warp >> 1;          // 0..3 : 32 M-rows each
    const int wn   = warp & 1;           // 0..1 : 64 N-cols each
    const int bm   = blockIdx.x * 128;
    const int bn   = blockIdx.y * 128;

    // loader mapping (A and B use the same shape: 128 rows x 16 k)
    const int lrow = tid >> 1;           // 0..127
    const int lk   = (tid & 1) * 8;      // 0 or 8

    float acc[2][8][4];
    #pragma unroll
    for (int i = 0; i < 2; ++i) {
        #pragma unroll
        for (int j = 0; j < 8; ++j) {
            #pragma unroll
            for (int q = 0; q < 4; ++q) { acc[i][j][q] = 0.f; }
        }
    }

    const int grow = bm + lrow;
    const bool arow_ok = (grow < M);
    const float4 z4 = make_float4(0.f, 0.f, 0.f, 0.f);
    const uint4  zu = make_uint4(0u, 0u, 0u, 0u);

    // prefetch regs
    float4 pa0 = z4, pa1 = z4;
    uint4  ph = zu, pl = zu, pbh, pbl;

    // prefetch k-tile 0
    if (A_SPLIT) {
        if (arow_ok) {
            ph = *(const uint4*)(Agh + (long)grow * lda + lk);
            pl = *(const uint4*)(Agl + (long)grow * lda + lk);
        }
    } else {
        if (arow_ok) {
            pa0 = *(const float4*)(A + (long)grow * lda + lk);
            pa1 = *(const float4*)(A + (long)grow * lda + lk + 4);
        }
    }
    pbh = *(const uint4*)(Wh + (long)(bn + lrow) * 1024 + wofs + lk);
    pbl = *(const uint4*)(Wl + (long)(bn + lrow) * 1024 + wofs + lk);

    // store k-tile 0
    if (A_SPLIT) {
        *(uint4*)(sAh[0] + lrow * AROW + lk) = ph;
        *(uint4*)(sAl[0] + lrow * AROW + lk) = pl;
    } else {
        store_a8(sAh[0], sAl[0], lrow, lk, pa0, pa1);
    }
    *(uint4*)(sBh[0] + lrow * AROW + lk) = pbh;
    *(uint4*)(sBl[0] + lrow * AROW + lk) = pbl;
    __syncthreads();

    // ldmatrix per-thread coordinates (validated in R8)
    const int gq8 = lane >> 3;
    const int wi  = lane & 7;
    const int a_row = wm * 32 + wi + 8 * (gq8 & 1);
    const int a_kh  = (gq8 >> 1) * 8;
    const int b_row = wn * 64 + wi + 8 * (gq8 >> 1);
    const int b_kh  = (gq8 & 1) * 8;

    int cur = 0;
    for (int k0 = 0; k0 < K; k0 += 16) {
        const bool has_next = (k0 + 16) < K;
        if (has_next) {
            const int kk = k0 + 16;
            if (A_SPLIT) {
                if (arow_ok) {
                    ph = *(const uint4*)(Agh + (long)grow * lda + kk + lk);
                    pl = *(const uint4*)(Agl + (long)grow * lda + kk + lk);
                } else { ph = zu; pl = zu; }
            } else {
                if (arow_ok) {
                    pa0 = *(const float4*)(A + (long)grow * lda + kk + lk);
                    pa1 = *(const float4*)(A + (long)grow * lda + kk + lk + 4);
                }
            }
            pbh = *(const uint4*)(Wh + (long)(bn + lrow) * 1024 + wofs + kk + lk);
            pbl = *(const uint4*)(Wl + (long)(bn + lrow) * 1024 + wofs + kk + lk);
        }

        // fragments
        unsigned Ahf[2][4], Alf[2][4], Bhf[4][4], Blf[4][4];
        #pragma unroll
        for (int mt = 0; mt < 2; ++mt) {
            unsigned off = (unsigned)((a_row + mt * 16) * AROW + a_kh) * 2u;
            unsigned ah = (unsigned)__cvta_generic_to_shared(sAh[cur]) + off;
            unsigned al = (unsigned)__cvta_generic_to_shared(sAl[cur]) + off;
            ldsm4(Ahf[mt][0], Ahf[mt][1], Ahf[mt][2], Ahf[mt][3], ah);
            ldsm4(Alf[mt][0], Alf[mt][1], Alf[mt][2], Alf[mt][3], al);
        }
        #pragma unroll
        for (int p = 0; p < 4; ++p) {
            unsigned off = (unsigned)((b_row + p * 16) * AROW + b_kh) * 2u;
            unsigned bh = (unsigned)__cvta_generic_to_shared(sBh[cur]) + off;
            unsigned bl = (unsigned)__cvta_generic_to_shared(sBl[cur]) + off;
            ldsm4(Bhf[p][0], Bhf[p][1], Bhf[p][2], Bhf[p][3], bh);
            ldsm4(Blf[p][0], Blf[p][1], Blf[p][2], Blf[p][3], bl);
        }

        // 3-pass MMA: hi*hi + hi*lo + lo*hi
        #pragma unroll
        for (int mt = 0; mt < 2; ++mt) {
            #pragma unroll
            for (int p = 0; p < 4; ++p) {
                #pragma unroll
                for (int nh = 0; nh < 2; ++nh) {
                    float* c = acc[mt][p * 2 + nh];
                    mma16816(c, Ahf[mt][0], Ahf[mt][1], Ahf[mt][2], Ahf[mt][3],
                             Bhf[p][2 * nh], Bhf[p][2 * nh + 1]);
                    mma16816(c, Ahf[mt][0], Ahf[mt][1], Ahf[mt][2], Ahf[mt][3],
                             Blf[p][2 * nh], Blf[p][2 * nh + 1]);
                    mma16816(c, Alf[mt][0], Alf[mt][1], Alf[mt][2], Alf[mt][3],
                             Bhf[p][2 * nh], Bhf[p][2 * nh + 1]);
                }
            }
        }

        if (has_next) {
            const int nb = cur ^ 1;
            if (A_SPLIT) {
                *(uint4*)(sAh[nb] + lrow * AROW + lk) = ph;
                *(uint4*)(sAl[nb] + lrow * AROW + lk) = pl;
            } else {
                store_a8(sAh[nb], sAl[nb], lrow, lk, pa0, pa1);
            }
            *(uint4*)(sBh[nb] + lrow * AROW + lk) = pbh;
            *(uint4*)(sBl[nb] + lrow * AROW + lk) = pbl;
            __syncthreads();
            cur = nb;
        }
    }

    // epilogue
    const int gq  = lane >> 2;
    const int tig = lane & 3;
    #pragma unroll
    for (int mt = 0; mt < 2; ++mt) {
        #pragma unroll
        for (int rh = 0; rh < 2; ++rh) {
            const int row = bm + wm * 32 + mt * 16 + rh * 8 + gq;
            if (row >= M) continue;
            const bool leaf = LEAF_TANH && (row >= first_leaf);
            #pragma unroll
            for (int nt = 0; nt < 8; ++nt) {
                const int col = bn + wn * 64 + nt * 8 + 2 * tig;
                float v0 = acc[mt][nt][2 * rh + 0];
                float v1 = acc[mt][nt][2 * rh + 1];
                if (HAS_BIAS) { v0 += bias[col]; v1 += bias[col + 1]; }
                if (leaf) {
                    v0 = tanhf(v0); v1 = tanhf(v1);
                    *(float2*)(S + (long)row * MEM_DIM + col) = make_float2(v0, v1);
                    __nv_bfloat162 h, l;
                    split2(v0, v1, h, l);
                    *(__nv_bfloat162*)(Sh + (long)row * MEM_DIM + col) = h;
                    *(__nv_bfloat162*)(Sl + (long)row * MEM_DIM + col) = l;
                } else {
                    *(float2*)(Cmat + (long)row * MEM_DIM + col) = make_float2(v0, v1);
                }
            }
        }
    }
}

// ---------------------------------------------------------------------------
// Combine (warp-per-child for C==8; generic fallback). Writes fp32 states and
// bf16 split copies (A operand for upper-level P-GEMMs).
// ---------------------------------------------------------------------------
__global__ __launch_bounds__(256)
void rcnn_combine(int lo,
                  const int*   __restrict__ cidx,
                  const int*   __restrict__ cdep,
                  const int*   __restrict__ counts,
                  const float* __restrict__ X,
                  const float* __restrict__ D,
                  const float* __restrict__ P,
                  float*       __restrict__ S,
                  __nv_bfloat16* __restrict__ Sh,
                  __nv_bfloat16* __restrict__ Sl) {
    const int i   = lo + (int)blockIdx.x;
    const int tid = threadIdx.x;
    const int cnt = counts[i];

    __shared__ float r[MAX_CH * MEM_DIM];

    if (cnt == 8) {
        const int w = tid >> 5;
        const int l = tid & 31;
        const int g = l * 8;

        const int c  = cidx[i * MAX_CH + w];
        const int dv = cdep[i * MAX_CH + w];

        const float4 x0 = *(const float4*)(X + (long)i  * MEM_DIM + g);
        const float4 x1 = *(const float4*)(X + (long)i  * MEM_DIM + g + 4);
        const float4 d0 = *(const float4*)(D + (long)dv * MEM_DIM + g);
        const float4 d1 = *(const float4*)(D + (long)dv * MEM_DIM + g + 4);
        const float4 p0 = *(const float4*)(P + (long)c  * MEM_DIM + g);
        const float4 p1 = *(const float4*)(P + (long)c  * MEM_DIM + g + 4);

        float m = tanhf(x0.x + d0.x + p0.x);
        m = fmaxf(m, tanhf(x0.y + d0.y + p0.y));
        m = fmaxf(m, tanhf(x0.z + d0.z + p0.z));
        m = fmaxf(m, tanhf(x0.w + d0.w + p0.w));
        m = fmaxf(m, tanhf(x1.x + d1.x + p1.x));
        m = fmaxf(m, tanhf(x1.y + d1.y + p1.y));
        m = fmaxf(m, tanhf(x1.z + d1.z + p1.z));
        m = fmaxf(m, tanhf(x1.w + d1.w + p1.w));

        const long o = (long)i * MEM_DIM + w * 32 + l;
        S[o] = m;
        __nv_bfloat16 h = __float2bfloat16(m);
        Sh[o] = h;
        Sl[o] = __float2bfloat16(m - __bfloat162float(h));
        return;
    }

    // generic path (rare: C != 8, e.g. node 2047 with C=7)
    const int f = tid;
    const float x = X[(long)i * MEM_DIM + f];
    const long o = (long)i * MEM_DIM + f;

    if (cnt == 0) {
        float v = tanhf(x);
        S[o] = v;
        __nv_bfloat16 h = __float2bfloat16(v);
        Sh[o] = h;
        Sl[o] = __float2bfloat16(v - __bfloat162float(h));
        return;
    }
    const int C = cnt;

    for (int k = 0; k < C; ++k) {
        int c  = cidx[i * MAX_CH + k];
        int dv = cdep[i * MAX_CH + k];
        r[k * MEM_DIM + f] = tanhf(x + D[dv * MEM_DIM + f] + P[(long)c * MEM_DIM + f]);
    }
    __syncthreads();

    float mx = -3.402823466e38f;
    for (int t = 0; t < C; ++t) {
        int j = f * C + t;
        mx = fmaxf(mx, r[(j >> 8) * MEM_DIM + (j & 255)]);
    }
    S[o] = mx;
    __nv_bfloat16 h = __float2bfloat16(mx);
    Sh[o] = h;
    Sl[o] = __float2bfloat16(mx - __bfloat162float(h));
}

// ---------------------------------------------------------------------------
extern "C" void kernel_launch(void* const* d_in, const int* in_sizes, int n_in,
                              void* d_out, int out_size) {
    const float* inputs    = (const float*)d_in[0];   // [N, 512]
    const float* W         = (const float*)d_in[1];   // [256, 1024]
    const float* bvec      = (const float*)d_in[2];   // [256]
    const float* deprel    = (const float*)d_in[3];   // [64, 256]
    const int*   child_idx = (const int*)  d_in[4];   // [N, 8]
    const int*   child_dep = (const int*)  d_in[5];   // [N, 8]
    const int*   counts    = (const int*)  d_in[6];   // [N]
    float*       states    = (float*)d_out;           // [N, 256]

    float *X = 0, *P = 0, *D = 0;
    __nv_bfloat16 *Wh = 0, *Wl = 0, *Sh = 0, *Sl = 0;
    cudaGetSymbolAddress((void**)&X,  g_X);
    cudaGetSymbolAddress((void**)&P,  g_P);
    cudaGetSymbolAddress((void**)&D,  g_D);
    cudaGetSymbolAddress((void**)&Wh, g_Wh);
    cudaGetSymbolAddress((void**)&Wl, g_Wl);
    cudaGetSymbolAddress((void**)&Sh, g_Sh);
    cudaGetSymbolAddress((void**)&Sl, g_Sl);

    const int N = in_sizes[0] / IN_DIM;               // 16384
    const int first_leaf = (N + MAX_CH - 2) / MAX_CH; // 2048

    // Phase -1: split W once (bf16 hi/lo), reused by every GEMM.
    split_w<<<256, 256>>>(W, Wh, Wl);

    // Phase 0: input projection + bias; leaf rows tanh'd + split in epilogue.
    rcnn_gemm_mma<false, true, true><<<dim3((unsigned)((N + 127) / 128), 2), 256>>>(
        inputs, 0, 0, IN_DIM, Wh, Wl, 0, bvec, X, N, IN_DIM,
        states, Sh, Sl, first_leaf);
    // deprel projection (tiny)
    rcnn_gemm_mma<false, false, false><<<dim3(1, 2), 256>>>(
        deprel, 0, 0, MEM_DIM, Wh, Wl, IN_DIM, 0, D, VOCAB, MEM_DIM, 0, 0, 0, 0);

    // Level starts: s[L] = (8^L - 1)/7
    long s[12];
    s[0] = 0;
    int nl = 0;
    while (s[nl] < N) { s[nl + 1] = 8 * s[nl] + 1; nl++; }

    // Internal levels, bottom-up
    for (int L = nl - 1; L >= 0; --L) {
        long lo = s[L];
        long hi = s[L + 1] - 1;
        if (hi > first_leaf - 1) hi = first_leaf - 1;
        if (lo > hi) continue;

        long clo = 8 * lo + 1;
        long chi = 8 * hi + 8;
        if (chi > N - 1) chi = N - 1;
        int Mc = (int)(chi - clo + 1);

        // P[j] = states[j] @ W_ch^T, A read pre-split from Sh/Sl
        rcnn_gemm_mma<true, false, false><<<dim3((unsigned)((Mc + 127) / 128), 2), 256>>>(
            0, Sh + clo * MEM_DIM, Sl + clo * MEM_DIM, MEM_DIM,
            Wh, Wl, IN_DIM + MEM_DIM, 0, P + clo * MEM_DIM, Mc, MEM_DIM, 0, 0, 0, 0);

        rcnn_combine<<<(unsigned)(hi - lo + 1), 256>>>(
            (int)lo, child_idx, child_dep, counts, X, D, P, states, Sh, Sl);
    }
}